// round 13
// baseline (speedup 1.0000x reference)
#include <cuda_runtime.h>
#include <math.h>
#include <stdint.h>

#define NG    2048
#define NPG   24
#define EPG   288
#define KGB   32
#define EMB   32
#define DH    64
#define NT    256
#define NPAIR (NPG*NPG)          // 576
#define NATOM 10
#define EPC   128                // edges per edge-CTA
#define NECTA (NG*EPG/EPC)       // 4608
#define GRID  (NG + NECTA)       // 6656 = 13*512

typedef unsigned long long ull;

// ---------------- packed fp32x2 helpers ----------------
__device__ __forceinline__ ull pk2(float lo, float hi) {
    ull r; asm("mov.b64 %0, {%1, %2};" : "=l"(r) : "f"(lo), "f"(hi)); return r;
}
__device__ __forceinline__ void upk2(ull v, float& lo, float& hi) {
    asm("mov.b64 {%0, %1}, %2;" : "=f"(lo), "=f"(hi) : "l"(v));
}
__device__ __forceinline__ ull ffma2(ull a, ull b, ull c) {
    ull d; asm("fma.rn.f32x2 %0, %1, %2, %3;" : "=l"(d) : "l"(a), "l"(b), "l"(c)); return d;
}
__device__ __forceinline__ float fex2(float x) {
    float r; asm("ex2.approx.f32 %0, %1;" : "=f"(r) : "f"(x)); return r;
}
__device__ __forceinline__ uint32_t tf32r(float x) {
    uint32_t r; asm("cvt.rna.tf32.f32 %0, %1;" : "=r"(r) : "f"(x)); return r;
}
__device__ __forceinline__ void mma_tf32(float* c, const uint32_t* a,
                                         uint32_t b0, uint32_t b1) {
    asm volatile("mma.sync.aligned.m16n8k8.row.col.f32.tf32.tf32.f32 "
        "{%0,%1,%2,%3}, {%4,%5,%6,%7}, {%8,%9}, {%0,%1,%2,%3};"
        : "+f"(c[0]), "+f"(c[1]), "+f"(c[2]), "+f"(c[3])
        : "r"(a[0]), "r"(a[1]), "r"(a[2]), "r"(a[3]), "r"(b0), "r"(b1));
}

// ---------------- node-path smem layout (words) ----------------
#define N_XV    0                          // 576
#define N_S     (N_XV   + NPAIR)
#define N_GNF   (N_S    + NPG*KGB)
#define N_WEP   (N_GNF  + NPG*EMB)
#define N_MUL   (N_WEP  + KGB*EMB)
#define N_BIAS  (N_MUL  + NATOM*NATOM)
#define N_C1    (N_BIAS + NATOM*NATOM)
#define N_C2    (N_C1   + KGB)
#define N_NORM  (N_C2   + KGB)
#define N_BEP   (N_NORM + KGB)
#define N_BN    (N_BEP  + EMB)
#define N_AE    (N_BN   + DH)
#define N_POS   (N_AE   + NATOM*EMB)
#define N_Z     (N_POS  + NPG*3)
#define NODE_WORDS (N_Z + NPG)             // 3944

// ---------------- edge-path smem layout (words) ----------------
#define WTPAD  72
#define STPAD  72
#define E_WT    0                          // 2304
#define E_STG   (E_WT + KGB*WTPAD)         // 4608
#define E_MUL   (E_STG + 8*8*STPAD)        // 100
#define E_BIAS  (E_MUL + NATOM*NATOM)      // 100
#define E_C1    (E_BIAS + NATOM*NATOM)     // 32
#define E_C2    (E_C1 + KGB)
#define E_NORM  (E_C2 + KGB)
#define E_BE    (E_NORM + KGB)             // 64
#define EDGE_WORDS (E_BE + DH)             // 7272

#define SMEM_WORDS (EDGE_WORDS > NODE_WORDS ? EDGE_WORDS : NODE_WORDS)
#define SMEM_BYTES (SMEM_WORDS * 4)

extern __shared__ float sm[];

// =====================================================================
// node path: per-graph node features
// =====================================================================
__device__ __forceinline__ void node_path(
    int g, int tid,
    const int* __restrict__ z, const float* __restrict__ pos,
    const float* __restrict__ atom_emb,
    const float* __restrict__ Wep, const float* __restrict__ bep,
    const float* __restrict__ means, const float* __restrict__ stds,
    const float* __restrict__ gmul, const float* __restrict__ gbias,
    const float* __restrict__ Wn, const float* __restrict__ bn,
    float* __restrict__ out_nodes)
{
    const int zbase = g * NPG;

    float* Xv    = sm + N_XV;
    float* Ssum  = sm + N_S;
    float* Gnf   = sm + N_GNF;
    ull*   sWep2 = (ull*)(sm + N_WEP);
    float* sMul  = sm + N_MUL;
    float* sBias = sm + N_BIAS;
    float* sC1   = sm + N_C1;
    float* sC2   = sm + N_C2;
    float* sNorm = sm + N_NORM;
    float* sBep  = sm + N_BEP;
    float* sBn   = sm + N_BN;
    float* sAe   = sm + N_AE;
    float* sPos  = sm + N_POS;
    int*   sZ    = (int*)(sm + N_Z);

    if (tid < NPG) sZ[tid] = z[zbase + tid];
    for (int t = tid; t < NPG*3; t += NT) sPos[t] = pos[zbase*3 + t];
    for (int t = tid; t < (KGB/2)*EMB; t += NT) {
        int kk = t >> 5, m = t & 31;
        sWep2[kk * EMB + m] = pk2(Wep[(2*kk)*EMB + m], Wep[(2*kk+1)*EMB + m]);
    }
    for (int t = tid; t < NATOM*NATOM; t += NT) { sMul[t] = gmul[t]; sBias[t] = gbias[t]; }
    if (tid < KGB) {
        float s = fabsf(stds[tid]) + 1e-5f;
        float ik = 1.0f / s;
        float c1 = 0.8493218002880191f * ik;        // sqrt(0.5*log2(e))/s
        sC1[tid] = c1;
        sC2[tid] = -means[tid] * c1;
        sNorm[tid] = 0.3989422804014327f * ik;
    }
    if (tid >= KGB && tid < 2*KGB) sBep[tid - KGB] = bep[tid - KGB];
    if (tid >= 64 && tid < 128)  sBn[tid - 64] = bn[tid - 64];
    for (int t = tid; t < NATOM*EMB; t += NT) sAe[t] = atom_emb[t];
    __syncthreads();

    for (int p = tid; p < NPAIR; p += NT) {
        int i = p / NPG;
        int j = p - i * NPG;
        float dx = sPos[i*3+0] - sPos[j*3+0];
        float dy = sPos[i*3+1] - sPos[j*3+1];
        float dz = sPos[i*3+2] - sPos[j*3+2];
        float sq = dx*dx + dy*dy + dz*dz;
        float dist = (sq == 0.0f) ? 0.0f : sqrtf(sq);
        int et = sZ[i] * NATOM + sZ[j];
        Xv[p] = sMul[et] * dist + sBias[et];
    }
    __syncthreads();

    {
        const int k = tid & 31;
        const float c1k = sC1[k], c2k = sC2[k], nk = sNorm[k];
        for (int t = tid; t < NPG * KGB; t += NT) {
            int i = t >> 5;
            const float* xr = Xv + i * NPG;
            float s0 = 0.0f, s1 = 0.0f;
            #pragma unroll
            for (int j = 0; j < NPG; j += 2) {
                float b0 = fmaf(xr[j],   c1k, c2k);
                float b1 = fmaf(xr[j+1], c1k, c2k);
                s0 += fex2(-b0 * b0);
                s1 += fex2(-b1 * b1);
            }
            Ssum[t] = nk * (s0 + s1);
        }
    }
    __syncthreads();

    for (int t = tid; t < NPG * EMB; t += NT) {
        int i = t >> 5, m = t & 31;
        const ull* s2 = (const ull*)(Ssum + i * KGB);
        ull acc = 0;
        #pragma unroll
        for (int kk = 0; kk < KGB/2; ++kk)
            acc = ffma2(s2[kk], sWep2[kk * EMB + m], acc);
        float lo, hi; upk2(acc, lo, hi);
        Gnf[t] = sAe[sZ[i] * EMB + m] + sBep[m] + lo + hi;
    }
    __syncthreads();

    {
        const int d = tid & (DH - 1);
        const int isub = tid >> 6;
        ull w[EMB/2];
        #pragma unroll
        for (int mm = 0; mm < EMB/2; ++mm)
            w[mm] = pk2(Wn[(2*mm)*DH + d], Wn[(2*mm+1)*DH + d]);
        const float bd = sBn[d];
        for (int i = isub; i < NPG; i += NT/DH) {
            const ull* g2 = (const ull*)(Gnf + i * EMB);
            ull a0 = 0, a1 = 0;
            #pragma unroll
            for (int mm = 0; mm < EMB/2; mm += 2) {
                a0 = ffma2(g2[mm],   w[mm],   a0);
                a1 = ffma2(g2[mm+1], w[mm+1], a1);
            }
            float l0, h0, l1, h1; upk2(a0, l0, h0); upk2(a1, l1, h1);
            out_nodes[(size_t)(zbase + i) * DH + d] = bd + l0 + h0 + l1 + h1;
        }
    }
}

// =====================================================================
// edge path: 128 edges/CTA; x recomputed from pos/z (no XvG dependency)
// =====================================================================
__device__ __forceinline__ void edge_path(
    int ecta, int tid,
    const int* __restrict__ z, const float* __restrict__ pos,
    const int* __restrict__ edge_index,
    const float* __restrict__ We, const float* __restrict__ be,
    const float* __restrict__ means, const float* __restrict__ stds,
    const float* __restrict__ gmul, const float* __restrict__ gbias,
    float* __restrict__ out_edges, int E)
{
    const int wid  = tid >> 5;
    const int lane = tid & 31;
    const int e0   = ecta * EPC;

    uint32_t* WtU  = (uint32_t*)(sm + E_WT);
    float*    sMul = sm + E_MUL;
    float*    sBias= sm + E_BIAS;
    float*    sC1  = sm + E_C1;
    float*    sC2  = sm + E_C2;
    float*    sNm  = sm + E_NORM;
    float*    sBe  = sm + E_BE;

    const int g4 = lane >> 2;          // 0..7
    const int t4 = lane & 3;           // 0..3
    const int m0 = wid * 16;

    // issue edge-index LDGs first (overlap with table setup)
    const int el0 = e0 + m0 + g4;
    const int el1 = el0 + 8;
    int j0 = edge_index[el0];          // src (= col j)
    int j1 = edge_index[el1];
    int i0 = edge_index[E + el0];      // dst (= row i)
    int i1 = edge_index[E + el1];

    // tables
    if (tid < KGB) {
        float s = fabsf(stds[tid]) + 1e-5f;
        float ik = 1.0f / s;
        float c1 = 0.8493218002880191f * ik;
        sC1[tid] = c1;
        sC2[tid] = -means[tid] * c1;
        sNm[tid] = 0.3989422804014327f * ik;
    }
    if (tid >= 32 && tid < 96) sBe[tid - 32] = be[tid - 32];
    for (int t = tid; t < NATOM*NATOM; t += NT) { sMul[t] = gmul[t]; sBias[t] = gbias[t]; }
    for (int t = tid; t < KGB*DH; t += NT) {
        int k = t >> 6, n = t & 63;
        WtU[k * WTPAD + n] = tf32r(We[t]);
    }

    // dependent loads: pos + z for both edges (L2-hot)
    float ax0 = pos[i0*3+0] - pos[j0*3+0];
    float ay0 = pos[i0*3+1] - pos[j0*3+1];
    float az0 = pos[i0*3+2] - pos[j0*3+2];
    float ax1 = pos[i1*3+0] - pos[j1*3+0];
    float ay1 = pos[i1*3+1] - pos[j1*3+1];
    float az1 = pos[i1*3+2] - pos[j1*3+2];
    int   et0 = z[i0] * NATOM + z[j0];
    int   et1 = z[i1] * NATOM + z[j1];
    float sq0 = ax0*ax0 + ay0*ay0 + az0*az0;
    float sq1 = ax1*ax1 + ay1*ay1 + az1*az1;
    float dd0 = (sq0 == 0.0f) ? 0.0f : sqrtf(sq0);
    float dd1 = (sq1 == 0.0f) ? 0.0f : sqrtf(sq1);
    __syncthreads();
    float x0 = sMul[et0] * dd0 + sBias[et0];
    float x1 = sMul[et1] * dd1 + sBias[et1];

    // A fragments in place (rows m0+g4, m0+g4+8; cols k ≡ t4 mod 4)
    uint32_t A[16];
    #pragma unroll
    for (int ks = 0; ks < 4; ++ks) {
        #pragma unroll
        for (int h = 0; h < 2; ++h) {
            int k = ks*8 + t4 + h*4;
            float c1 = sC1[k], c2 = sC2[k], nm = sNm[k];
            float b0 = fmaf(x0, c1, c2);
            float b1 = fmaf(x1, c1, c2);
            A[ks*4 + h*2 + 0] = tf32r(nm * fex2(-b0 * b0));
            A[ks*4 + h*2 + 1] = tf32r(nm * fex2(-b1 * b1));
        }
    }

    // MMA + 2-pass staged epilogue (per-warp staging)
    {
        float* stg = sm + E_STG + wid * 8 * STPAD;
        float keep[16];

        #pragma unroll
        for (int nt = 0; nt < 8; ++nt) {
            float c[4] = {0.f, 0.f, 0.f, 0.f};
            #pragma unroll
            for (int ks = 0; ks < 4; ++ks) {
                uint32_t b0 = WtU[(ks*8 + t4)     * WTPAD + nt*8 + g4];
                uint32_t b1 = WtU[(ks*8 + t4 + 4) * WTPAD + nt*8 + g4];
                mma_tf32(c, A + ks*4, b0, b1);
            }
            *(float2*)(stg + g4 * STPAD + nt*8 + t4*2) = make_float2(c[0], c[1]);
            keep[nt*2]   = c[2];
            keep[nt*2+1] = c[3];
        }
        __syncwarp();

        const int colb = (lane & 7) * 4;
        const int rowb = lane >> 3;
        float4 b0 = *(const float4*)(sBe + colb);
        float4 b1 = *(const float4*)(sBe + colb + 32);

        #pragma unroll
        for (int p = 0; p < 2; ++p) {
            const int r = rowb + 4*p;
            float4 v0 = *(const float4*)(stg + r * STPAD + colb);
            float4 v1 = *(const float4*)(stg + r * STPAD + colb + 32);
            v0.x += b0.x; v0.y += b0.y; v0.z += b0.z; v0.w += b0.w;
            v1.x += b1.x; v1.y += b1.y; v1.z += b1.z; v1.w += b1.w;
            float* o = out_edges + (size_t)(e0 + m0 + r) * DH;
            *(float4*)(o + colb)      = v0;
            *(float4*)(o + colb + 32) = v1;
        }
        __syncwarp();

        #pragma unroll
        for (int nt = 0; nt < 8; ++nt)
            *(float2*)(stg + g4 * STPAD + nt*8 + t4*2) =
                make_float2(keep[nt*2], keep[nt*2+1]);
        __syncwarp();

        #pragma unroll
        for (int p = 0; p < 2; ++p) {
            const int r = rowb + 4*p;
            float4 v0 = *(const float4*)(stg + r * STPAD + colb);
            float4 v1 = *(const float4*)(stg + r * STPAD + colb + 32);
            v0.x += b0.x; v0.y += b0.y; v0.z += b0.z; v0.w += b0.w;
            v1.x += b1.x; v1.y += b1.y; v1.z += b1.z; v1.w += b1.w;
            float* o = out_edges + (size_t)(e0 + m0 + 8 + r) * DH;
            *(float4*)(o + colb)      = v0;
            *(float4*)(o + colb + 32) = v1;
        }
    }
}

// =====================================================================
// fused kernel: 13-block groups = 4 node CTAs + 9 edge CTAs (interleaved)
// =====================================================================
__global__ __launch_bounds__(NT, 4)
void gps_fused_kernel(const int* __restrict__ z,
                      const float* __restrict__ pos,
                      const int* __restrict__ edge_index,
                      const float* __restrict__ atom_emb,
                      const float* __restrict__ Wep,
                      const float* __restrict__ bep,
                      const float* __restrict__ means,
                      const float* __restrict__ stds,
                      const float* __restrict__ gmul,
                      const float* __restrict__ gbias,
                      const float* __restrict__ Wn,
                      const float* __restrict__ bn,
                      const float* __restrict__ We,
                      const float* __restrict__ be,
                      float* __restrict__ out_nodes,
                      float* __restrict__ out_edges,
                      int E)
{
    const int bid = blockIdx.x;
    const int grp = bid / 13;
    const int r   = bid % 13;
    const int tid = threadIdx.x;

    if (r < 4) {
        node_path(grp * 4 + r, tid, z, pos, atom_emb, Wep, bep,
                  means, stds, gmul, gbias, Wn, bn, out_nodes);
    } else {
        edge_path(grp * 9 + (r - 4), tid, z, pos, edge_index, We, be,
                  means, stds, gmul, gbias, out_edges, E);
    }
}

extern "C" void kernel_launch(void* const* d_in, const int* in_sizes, int n_in,
                              void* d_out, int out_size)
{
    const int*   z    = (const int*)  d_in[0];
    const float* pos  = (const float*)d_in[1];
    const int*   ei   = (const int*)  d_in[3];
    const float* ae   = (const float*)d_in[4];
    const float* Wep  = (const float*)d_in[5];
    const float* bep  = (const float*)d_in[6];
    const float* mea  = (const float*)d_in[7];
    const float* stds = (const float*)d_in[8];
    const float* gmul = (const float*)d_in[9];
    const float* gbia = (const float*)d_in[10];
    const float* Wn   = (const float*)d_in[11];
    const float* bn   = (const float*)d_in[12];
    const float* We   = (const float*)d_in[13];
    const float* be   = (const float*)d_in[14];

    const int N = in_sizes[0];          // 49152
    const int E = in_sizes[3] / 2;      // 589824

    float* out_nodes = (float*)d_out;
    float* out_edges = out_nodes + (size_t)N * DH;

    cudaFuncSetAttribute(gps_fused_kernel,
                         cudaFuncAttributeMaxDynamicSharedMemorySize, SMEM_BYTES);

    gps_fused_kernel<<<GRID, NT, SMEM_BYTES>>>(
        z, pos, ei, ae, Wep, bep, mea, stds, gmul, gbia,
        Wn, bn, We, be, out_nodes, out_edges, E);
}